// round 14
// baseline (speedup 1.0000x reference)
#include <cuda_runtime.h>
#include <cuda_fp16.h>
#include <math.h>
#include <stdint.h>

#define D_MODEL 1024
#define B_SZ    8
#define S_LEN   2048
#define ROWS    (B_SZ * S_LEN)   /* 16384 */

// ---------------- scratch (device globals) ----------------
__device__ __half g_h16[(size_t)ROWS * D_MODEL];
__device__ __half g_qkv16[(size_t)ROWS * 3 * D_MODEL];
__device__ __half g_sc16[(size_t)B_SZ * S_LEN * S_LEN];
__device__ __half g_x2h[(size_t)ROWS * D_MODEL];
__device__ __half g_fc16[(size_t)ROWS * 4 * D_MODEL];
__device__ __half g_waT16[(size_t)3072 * 1024];
__device__ __half g_wfT16[(size_t)4096 * 1024];
__device__ __half g_wpT16[(size_t)1024 * 4096];

// ---------------- helpers ----------------
__device__ __forceinline__ float gelu_exact(float x) {
    return 0.5f * x * (1.0f + erff(x * 0.70710678118654752f));
}
__device__ __forceinline__ float warp_sum(float v) {
    #pragma unroll
    for (int o = 16; o; o >>= 1) v += __shfl_xor_sync(0xffffffffu, v, o);
    return v;
}
__device__ __forceinline__ float warp_max(float v) {
    #pragma unroll
    for (int o = 16; o; o >>= 1) v = fmaxf(v, __shfl_xor_sync(0xffffffffu, v, o));
    return v;
}
__device__ __forceinline__ void cp16(uint32_t dst_smem, const void* gptr) {
    asm volatile("cp.async.ca.shared.global [%0], [%1], 16;"
                 :: "r"(dst_smem), "l"(gptr) : "memory");
}

// ---------------- LayerNorm, warp-per-row, coalesced ----------------
// 256 thr = 8 warps = 8 rows per block. No block barriers.
template <typename TI>
__global__ void ln_kernel(const TI* __restrict__ x, const float* __restrict__ w,
                          const float* __restrict__ b, __half* __restrict__ out) {
    const int lane = threadIdx.x & 31;
    const size_t row = (size_t)blockIdx.x * 8 + (threadIdx.x >> 5);
    __half* op = out + row * D_MODEL;

    float f[32];
    if (sizeof(TI) == 4) {
        const float* xp = (const float*)x + row * D_MODEL;
        #pragma unroll
        for (int j = 0; j < 8; j++) {
            float4 v = *(const float4*)(xp + lane * 4 + j * 128);
            f[j * 4 + 0] = v.x; f[j * 4 + 1] = v.y;
            f[j * 4 + 2] = v.z; f[j * 4 + 3] = v.w;
        }
    } else {
        const __half* xp = (const __half*)x + row * D_MODEL;
        #pragma unroll
        for (int j = 0; j < 4; j++) {
            uint4 raw = *(const uint4*)(xp + lane * 8 + j * 256);
            const __half2* hp = (const __half2*)&raw;
            #pragma unroll
            for (int l = 0; l < 4; l++) {
                float2 t = __half22float2(hp[l]);
                f[j * 8 + l * 2] = t.x; f[j * 8 + l * 2 + 1] = t.y;
            }
        }
    }

    float s = 0.0f, ss = 0.0f;
    #pragma unroll
    for (int i = 0; i < 32; i++) { s += f[i]; ss += f[i] * f[i]; }
    s  = warp_sum(s);
    ss = warp_sum(ss);
    float mu  = s * (1.0f / D_MODEL);
    float var = ss * (1.0f / D_MODEL) - mu * mu;
    float inv = rsqrtf(var + 1e-5f);

    if (sizeof(TI) == 4) {
        #pragma unroll
        for (int j = 0; j < 8; j++) {
            int base = lane * 4 + j * 128;
            float4 wv = *(const float4*)(w + base);
            float4 bv = *(const float4*)(b + base);
            uint2 st;
            __half2* hp = (__half2*)&st;
            hp[0] = __floats2half2_rn((f[j * 4 + 0] - mu) * inv * wv.x + bv.x,
                                      (f[j * 4 + 1] - mu) * inv * wv.y + bv.y);
            hp[1] = __floats2half2_rn((f[j * 4 + 2] - mu) * inv * wv.z + bv.z,
                                      (f[j * 4 + 3] - mu) * inv * wv.w + bv.w);
            *(uint2*)(op + base) = st;
        }
    } else {
        #pragma unroll
        for (int j = 0; j < 4; j++) {
            int base = lane * 8 + j * 256;
            uint4 st;
            __half2* hp = (__half2*)&st;
            #pragma unroll
            for (int l = 0; l < 4; l++) {
                float2 wv = *(const float2*)(w + base + l * 2);
                float2 bv = *(const float2*)(b + base + l * 2);
                hp[l] = __floats2half2_rn(
                    (f[j * 8 + l * 2] - mu) * inv * wv.x + bv.x,
                    (f[j * 8 + l * 2 + 1] - mu) * inv * wv.y + bv.y);
            }
            *(uint4*)(op + base) = st;
        }
    }
}

// ---------------- Softmax, warp-per-row over fp16 row of 2048, in-place ---
__global__ void softmax_kernel(__half* __restrict__ sc) {
    const int lane = threadIdx.x & 31;
    const size_t row = (size_t)blockIdx.x * 8 + (threadIdx.x >> 5);
    __half* p = sc + row * (size_t)S_LEN;

    uint4 raw[8];
    float f[64];
    #pragma unroll
    for (int i = 0; i < 8; i++) {
        raw[i] = ((uint4*)p)[lane + i * 32];
        const __half2* hp = (const __half2*)&raw[i];
        #pragma unroll
        for (int l = 0; l < 4; l++) {
            float2 t = __half22float2(hp[l]);
            f[i * 8 + l * 2] = t.x; f[i * 8 + l * 2 + 1] = t.y;
        }
    }
    float m = f[0];
    #pragma unroll
    for (int i = 1; i < 64; i++) m = fmaxf(m, f[i]);
    m = warp_max(m);
    float s = 0.0f;
    #pragma unroll
    for (int i = 0; i < 64; i++) { f[i] = expf(f[i] - m); s += f[i]; }
    s = warp_sum(s);
    float inv = 1.0f / s;
    #pragma unroll
    for (int i = 0; i < 8; i++) {
        __half2* hp = (__half2*)&raw[i];
        #pragma unroll
        for (int l = 0; l < 4; l++)
            hp[l] = __floats2half2_rn(f[i * 8 + l * 2] * inv,
                                      f[i * 8 + l * 2 + 1] * inv);
        ((uint4*)p)[lane + i * 32] = raw[i];
    }
}

// ---------------- transpose: dst[c][r] = (TO)src[r][c] ----------------
template <typename TI, typename TO>
__global__ void transpose_kernel(const TI* __restrict__ src, TO* __restrict__ dst,
                                 int lds, int ldd) {
    __shared__ float t[32][33];
    int bx = blockIdx.x * 32;
    int by = blockIdx.y * 32;
    int tx = threadIdx.x, ty = threadIdx.y;
    #pragma unroll
    for (int i = 0; i < 4; i++)
        t[ty + i * 8][tx] = (float)src[(size_t)(by + ty + i * 8) * lds + bx + tx];
    __syncthreads();
    #pragma unroll
    for (int i = 0; i < 4; i++)
        dst[(size_t)(bx + ty + i * 8) * ldd + by + tx] = (TO)t[tx][ty + i * 8];
}

// =================== fp16 mma.sync GEMM, 128x128x32, 4-stage, occ 2 ========
// C = act(alpha * A @ op(B) + bias) (+ residual)
// A [M,K] fp16 row-major.
// TRANSB=0: B [N,K] row-major (K-major), normal ldmatrix.
// TRANSB=1: B [K,N] row-major (N-major), ldmatrix.trans (e.g. V in qkv).
#define LDH 40                         /* A: 32 + 8 pad halves; 80 B stride */
#define LDBT 136                       /* trans-B: 128 + 8 pad; 272 B stride */
#define NSTAGE 4
#define A_BYTES (128 * LDH * 2)        /* 10240 */
#define BN_BYTES (128 * LDH * 2)       /* 10240: [n][k] */
#define BT_BYTES (32 * LDBT * 2)       /* 8704:  [k][n] */

template <bool TRANSB, bool BIAS, int ACT, bool RES, bool OUT16>
__global__ __launch_bounds__(256, 2)
void hgemm(const __half* __restrict__ A, const __half* __restrict__ B,
           const float* __restrict__ bias, const float* __restrict__ res,
           void* __restrict__ Cv,
           int K, int lda, int ldb, int ldc, int ldres,
           size_t sA, size_t sB, size_t sC, size_t sR, float alpha) {
    constexpr int B_BYTES = TRANSB ? BT_BYTES : BN_BYTES;
    constexpr int STAGE_BYTES = A_BYTES + B_BYTES;

    extern __shared__ char dsm[];
    const uint32_t sbase = (uint32_t)__cvta_generic_to_shared(dsm);

    const int bn = blockIdx.x, bm = blockIdx.y, bz = blockIdx.z;
    const __half* Ab = A + sA * bz + (size_t)bm * 128 * lda;
    const __half* Bb = TRANSB ? (B + sB * bz + (size_t)bn * 128)
                              : (B + sB * bz + (size_t)bn * 128 * ldb);

    const int tid  = threadIdx.x;
    const int lane = tid & 31;
    const int warp = tid >> 5;
    const int wm   = warp >> 1;
    const int wn   = warp & 1;

    const uint32_t a_off = (uint32_t)((lane & 15) * 80 + (lane >> 4) * 16);
    const uint32_t bn_row = (uint32_t)(((lane >> 4) << 3) + (lane & 7));
    const uint32_t bn_off = (uint32_t)(bn_row * 80 + ((lane >> 3) & 1) * 16);
    const uint32_t bt_off = (uint32_t)((lane & 15) * 272 + (lane >> 4) * 16);

    float acc[2][8][4];
    #pragma unroll
    for (int i = 0; i < 2; i++)
        #pragma unroll
        for (int j = 0; j < 8; j++)
            #pragma unroll
            for (int l = 0; l < 4; l++) acc[i][j][l] = 0.0f;

    const int T = K >> 5;

    auto stage = [&](int kt, int s) {
        const int k0 = kt << 5;
        const uint32_t sa = sbase + s * STAGE_BYTES;
        const uint32_t sb = sa + A_BYTES;
        const __half* gA = Ab + (size_t)(tid >> 1) * lda + k0 + (tid & 1) * 16;
        const uint32_t dA = sa + (tid >> 1) * 80 + (tid & 1) * 32;
        cp16(dA, gA);
        cp16(dA + 16, gA + 8);
        if (TRANSB) {
            const int kr = tid >> 3;
            const __half* gB = Bb + (size_t)(k0 + kr) * ldb + (tid & 7) * 16;
            const uint32_t dB = sb + kr * 272 + (tid & 7) * 32;
            cp16(dB, gB);
            cp16(dB + 16, gB + 8);
        } else {
            const __half* gB = Bb + (size_t)(tid >> 1) * ldb + k0 + (tid & 1) * 16;
            const uint32_t dB = sb + (tid >> 1) * 80 + (tid & 1) * 32;
            cp16(dB, gB);
            cp16(dB + 16, gB + 8);
        }
    };

    #pragma unroll
    for (int s = 0; s < NSTAGE; s++) {
        if (s < T) stage(s, s);
        asm volatile("cp.async.commit_group;" ::: "memory");
    }

    int buf = 0;
    for (int kt = 0; kt < T; kt++) {
        asm volatile("cp.async.wait_group %0;" :: "n"(NSTAGE - 1) : "memory");
        __syncthreads();

        const uint32_t sa = sbase + buf * STAGE_BYTES;
        const uint32_t sb = sa + A_BYTES;

        #pragma unroll
        for (int ks = 0; ks < 2; ks++) {
            uint32_t a[2][4];
            #pragma unroll
            for (int am = 0; am < 2; am++) {
                uint32_t addr = sa + (uint32_t)((wm * 32 + am * 16) * 80)
                              + a_off + ks * 32;
                asm volatile(
                    "ldmatrix.sync.aligned.m8n8.x4.shared.b16 {%0,%1,%2,%3}, [%4];"
                    : "=r"(a[am][0]), "=r"(a[am][1]), "=r"(a[am][2]), "=r"(a[am][3])
                    : "r"(addr));
            }
            uint32_t b[8][2];
            #pragma unroll
            for (int t = 0; t < 4; t++) {
                uint32_t r0, r1, r2, r3;
                if (TRANSB) {
                    uint32_t addr = sb + (uint32_t)(ks * 16 * 272)
                                  + (uint32_t)((wn * 64 + t * 16) * 2) + bt_off;
                    asm volatile(
                        "ldmatrix.sync.aligned.m8n8.x4.trans.shared.b16 {%0,%1,%2,%3}, [%4];"
                        : "=r"(r0), "=r"(r1), "=r"(r2), "=r"(r3)
                        : "r"(addr));
                } else {
                    uint32_t addr = sb + (uint32_t)((wn * 64 + t * 16) * 80)
                                  + bn_off + ks * 32;
                    asm volatile(
                        "ldmatrix.sync.aligned.m8n8.x4.shared.b16 {%0,%1,%2,%3}, [%4];"
                        : "=r"(r0), "=r"(r1), "=r"(r2), "=r"(r3)
                        : "r"(addr));
                }
                b[2 * t][0] = r0; b[2 * t][1] = r1;
                b[2 * t + 1][0] = r2; b[2 * t + 1][1] = r3;
            }
            #pragma unroll
            for (int am = 0; am < 2; am++)
                #pragma unroll
                for (int an = 0; an < 8; an++) {
                    asm volatile(
                        "mma.sync.aligned.m16n8k16.row.col.f32.f16.f16.f32 "
                        "{%0,%1,%2,%3}, {%4,%5,%6,%7}, {%8,%9}, {%0,%1,%2,%3};"
                        : "+f"(acc[am][an][0]), "+f"(acc[am][an][1]),
                          "+f"(acc[am][an][2]), "+f"(acc[am][an][3])
                        : "r"(a[am][0]), "r"(a[am][1]), "r"(a[am][2]), "r"(a[am][3]),
                          "r"(b[an][0]), "r"(b[an][1]));
                }
        }
        __syncthreads();
        if (kt + NSTAGE < T) stage(kt + NSTAGE, buf);
        asm volatile("cp.async.commit_group;" ::: "memory");
        buf = (buf + 1 == NSTAGE) ? 0 : buf + 1;
    }

    // ---- epilogue ----
    const int q  = lane >> 2;
    const int r2 = (lane & 3) * 2;
    #pragma unroll
    for (int am = 0; am < 2; am++) {
        int row0 = bm * 128 + wm * 32 + am * 16 + q;
        int row1 = row0 + 8;
        #pragma unroll
        for (int an = 0; an < 8; an++) {
            int col = bn * 128 + wn * 64 + an * 8 + r2;
            float v00 = acc[am][an][0] * alpha;
            float v01 = acc[am][an][1] * alpha;
            float v10 = acc[am][an][2] * alpha;
            float v11 = acc[am][an][3] * alpha;
            if (BIAS) {
                float2 bv = *(const float2*)(bias + col);
                v00 += bv.x; v01 += bv.y; v10 += bv.x; v11 += bv.y;
            }
            if (ACT == 1) {
                v00 = gelu_exact(v00); v01 = gelu_exact(v01);
                v10 = gelu_exact(v10); v11 = gelu_exact(v11);
            }
            if (RES) {
                float2 r0 = *(const float2*)(res + sR * bz + (size_t)row0 * ldres + col);
                float2 r1 = *(const float2*)(res + sR * bz + (size_t)row1 * ldres + col);
                v00 += r0.x; v01 += r0.y; v10 += r1.x; v11 += r1.y;
            }
            if (OUT16) {
                __half* Cb = (__half*)Cv + sC * bz;
                *(__half2*)(Cb + (size_t)row0 * ldc + col) = __floats2half2_rn(v00, v01);
                *(__half2*)(Cb + (size_t)row1 * ldc + col) = __floats2half2_rn(v10, v11);
            } else {
                float* Cb = (float*)Cv + sC * bz;
                *(float2*)(Cb + (size_t)row0 * ldc + col) = make_float2(v00, v01);
                *(float2*)(Cb + (size_t)row1 * ldc + col) = make_float2(v10, v11);
            }
        }
    }
}

#define GSMEM_N (NSTAGE * (A_BYTES + BN_BYTES))   /* 81920 */
#define GSMEM_T (NSTAGE * (A_BYTES + BT_BYTES))   /* 75776 */

// ---------------- launch ----------------
extern "C" void kernel_launch(void* const* d_in, const int* in_sizes, int n_in,
                              void* d_out, int out_size) {
    const float* x      = (const float*)d_in[0];
    const float* ln1_w  = (const float*)d_in[1];
    const float* ln1_b  = (const float*)d_in[2];
    const float* W_attn = (const float*)d_in[3];
    const float* b_attn = (const float*)d_in[4];
    const float* ln2_w  = (const float*)d_in[5];
    const float* ln2_b  = (const float*)d_in[6];
    const float* W_fc   = (const float*)d_in[7];
    const float* b_fc   = (const float*)d_in[8];
    const float* W_proj = (const float*)d_in[9];
    const float* b_proj = (const float*)d_in[10];
    float* out = (float*)d_out;

    void* p;
    cudaGetSymbolAddress(&p, g_h16);    __half* h    = (__half*)p;
    cudaGetSymbolAddress(&p, g_qkv16);  __half* qkv  = (__half*)p;
    cudaGetSymbolAddress(&p, g_sc16);   __half* sc   = (__half*)p;
    cudaGetSymbolAddress(&p, g_x2h);    __half* x2   = (__half*)p;
    cudaGetSymbolAddress(&p, g_fc16);   __half* fcb  = (__half*)p;
    cudaGetSymbolAddress(&p, g_waT16);  __half* waT  = (__half*)p;
    cudaGetSymbolAddress(&p, g_wfT16);  __half* wfT  = (__half*)p;
    cudaGetSymbolAddress(&p, g_wpT16);  __half* wpT  = (__half*)p;

    cudaFuncSetAttribute(hgemm<false, true, 0, false, true>,
                         cudaFuncAttributeMaxDynamicSharedMemorySize, GSMEM_N);
    cudaFuncSetAttribute(hgemm<false, false, 0, false, true>,
                         cudaFuncAttributeMaxDynamicSharedMemorySize, GSMEM_N);
    cudaFuncSetAttribute(hgemm<true, false, 0, true, true>,
                         cudaFuncAttributeMaxDynamicSharedMemorySize, GSMEM_T);
    cudaFuncSetAttribute(hgemm<false, true, 1, false, true>,
                         cudaFuncAttributeMaxDynamicSharedMemorySize, GSMEM_N);
    cudaFuncSetAttribute(hgemm<false, true, 0, false, false>,
                         cudaFuncAttributeMaxDynamicSharedMemorySize, GSMEM_N);

    dim3 blk(256);
    dim3 tblk(32, 8);

    // weight transposes -> K-major fp16
    transpose_kernel<float, __half><<<dim3(96, 32), tblk>>>(W_attn, waT, 3072, 1024);
    transpose_kernel<float, __half><<<dim3(128, 32), tblk>>>(W_fc, wfT, 4096, 1024);
    transpose_kernel<float, __half><<<dim3(32, 128), tblk>>>(W_proj, wpT, 1024, 4096);

    // 1) h = LN1(x) -> fp16  (warp-per-row, coalesced)
    ln_kernel<float><<<ROWS / 8, blk>>>(x, ln1_w, ln1_b, h);

    // 2) qkv = h @ W_attn + b_attn -> fp16 [16384,3072]
    hgemm<false, true, 0, false, true><<<dim3(24, 128, 1), blk, GSMEM_N>>>(
        h, waT, b_attn, nullptr, qkv,
        1024, 1024, 1024, 3072, 0, 0, 0, 0, 0, 1.0f);

    // 3) scores = (q @ k^T)/sqrt(D) -> fp16
    hgemm<false, false, 0, false, true><<<dim3(16, 16, 8), blk, GSMEM_N>>>(
        qkv, qkv + 1024, nullptr, nullptr, sc,
        1024, 3072, 3072, 2048, 0,
        (size_t)S_LEN * 3072, (size_t)S_LEN * 3072, (size_t)S_LEN * S_LEN, 0,
        0.03125f);

    // 4) softmax (warp-per-row, coalesced, fp16 in/out)
    softmax_kernel<<<ROWS / 8, blk>>>(sc);

    // 5) x2 = x + attn @ V -> fp16  (trans-B: V = qkv[:, 2048:] as [K,N])
    hgemm<true, false, 0, true, true><<<dim3(8, 16, 8), blk, GSMEM_T>>>(
        sc, qkv + 2048, nullptr, x, x2,
        2048, 2048, 3072, 1024, 1024,
        (size_t)S_LEN * S_LEN, (size_t)S_LEN * 3072,
        (size_t)S_LEN * 1024, (size_t)S_LEN * 1024, 1.0f);

    // 6) h = LN2(x2) -> fp16  (warp-per-row, coalesced, fp16 input)
    ln_kernel<__half><<<ROWS / 8, blk>>>(x2, ln2_w, ln2_b, h);

    // 7) fc = gelu(h @ W_fc + b_fc) -> fp16 [16384,4096]
    hgemm<false, true, 1, false, true><<<dim3(32, 128, 1), blk, GSMEM_N>>>(
        h, wfT, b_fc, nullptr, fcb,
        1024, 1024, 1024, 4096, 0, 0, 0, 0, 0, 1.0f);

    // 8) out = fc @ W_proj + b_proj -> fp32 [16384,1024]
    hgemm<false, true, 0, false, false><<<dim3(8, 128, 1), blk, GSMEM_N>>>(
        fcb, wpT, b_proj, nullptr, out,
        4096, 4096, 4096, 1024, 0, 0, 0, 0, 0, 1.0f);
}

// round 15
// speedup vs baseline: 1.0211x; 1.0211x over previous
#include <cuda_runtime.h>
#include <cuda_fp16.h>
#include <math.h>
#include <stdint.h>

#define D_MODEL 1024
#define B_SZ    8
#define S_LEN   2048
#define ROWS    (B_SZ * S_LEN)   /* 16384 */

// ---------------- scratch (device globals) ----------------
__device__ __half g_h16[(size_t)ROWS * D_MODEL];
__device__ __half g_qkv16[(size_t)ROWS * 3 * D_MODEL];
__device__ __half g_sc16[(size_t)B_SZ * S_LEN * S_LEN];
__device__ __half g_x2h[(size_t)ROWS * D_MODEL];
__device__ __half g_fc16[(size_t)ROWS * 4 * D_MODEL];
__device__ __half g_waT16[(size_t)3072 * 1024];
__device__ __half g_wfT16[(size_t)4096 * 1024];
__device__ __half g_wpT16[(size_t)1024 * 4096];

// ---------------- helpers ----------------
__device__ __forceinline__ float gelu_exact(float x) {
    return 0.5f * x * (1.0f + erff(x * 0.70710678118654752f));
}
__device__ __forceinline__ float warp_sum(float v) {
    #pragma unroll
    for (int o = 16; o; o >>= 1) v += __shfl_xor_sync(0xffffffffu, v, o);
    return v;
}
__device__ __forceinline__ float warp_max(float v) {
    #pragma unroll
    for (int o = 16; o; o >>= 1) v = fmaxf(v, __shfl_xor_sync(0xffffffffu, v, o));
    return v;
}
__device__ __forceinline__ void cp16(uint32_t dst_smem, const void* gptr) {
    asm volatile("cp.async.ca.shared.global [%0], [%1], 16;"
                 :: "r"(dst_smem), "l"(gptr) : "memory");
}

// ---------------- LayerNorm, warp-per-row, coalesced ----------------
// 256 thr = 8 warps = 8 rows per block. No block barriers.
template <typename TI>
__global__ void ln_kernel(const TI* __restrict__ x, const float* __restrict__ w,
                          const float* __restrict__ b, __half* __restrict__ out) {
    const int lane = threadIdx.x & 31;
    const size_t row = (size_t)blockIdx.x * 8 + (threadIdx.x >> 5);
    __half* op = out + row * D_MODEL;

    float f[32];
    if (sizeof(TI) == 4) {
        const float* xp = (const float*)x + row * D_MODEL;
        #pragma unroll
        for (int j = 0; j < 8; j++) {
            float4 v = *(const float4*)(xp + lane * 4 + j * 128);
            f[j * 4 + 0] = v.x; f[j * 4 + 1] = v.y;
            f[j * 4 + 2] = v.z; f[j * 4 + 3] = v.w;
        }
    } else {
        const __half* xp = (const __half*)x + row * D_MODEL;
        #pragma unroll
        for (int j = 0; j < 4; j++) {
            uint4 raw = *(const uint4*)(xp + lane * 8 + j * 256);
            const __half2* hp = (const __half2*)&raw;
            #pragma unroll
            for (int l = 0; l < 4; l++) {
                float2 t = __half22float2(hp[l]);
                f[j * 8 + l * 2] = t.x; f[j * 8 + l * 2 + 1] = t.y;
            }
        }
    }

    float s = 0.0f, ss = 0.0f;
    #pragma unroll
    for (int i = 0; i < 32; i++) { s += f[i]; ss += f[i] * f[i]; }
    s  = warp_sum(s);
    ss = warp_sum(ss);
    float mu  = s * (1.0f / D_MODEL);
    float var = ss * (1.0f / D_MODEL) - mu * mu;
    float inv = rsqrtf(var + 1e-5f);

    if (sizeof(TI) == 4) {
        #pragma unroll
        for (int j = 0; j < 8; j++) {
            int base = lane * 4 + j * 128;
            float4 wv = *(const float4*)(w + base);
            float4 bv = *(const float4*)(b + base);
            uint2 st;
            __half2* hp = (__half2*)&st;
            hp[0] = __floats2half2_rn((f[j * 4 + 0] - mu) * inv * wv.x + bv.x,
                                      (f[j * 4 + 1] - mu) * inv * wv.y + bv.y);
            hp[1] = __floats2half2_rn((f[j * 4 + 2] - mu) * inv * wv.z + bv.z,
                                      (f[j * 4 + 3] - mu) * inv * wv.w + bv.w);
            *(uint2*)(op + base) = st;
        }
    } else {
        #pragma unroll
        for (int j = 0; j < 4; j++) {
            int base = lane * 8 + j * 256;
            uint4 st;
            __half2* hp = (__half2*)&st;
            #pragma unroll
            for (int l = 0; l < 4; l++) {
                float2 wv = *(const float2*)(w + base + l * 2);
                float2 bv = *(const float2*)(b + base + l * 2);
                hp[l] = __floats2half2_rn(
                    (f[j * 8 + l * 2] - mu) * inv * wv.x + bv.x,
                    (f[j * 8 + l * 2 + 1] - mu) * inv * wv.y + bv.y);
            }
            *(uint4*)(op + base) = st;
        }
    }
}

// ---------------- Softmax, warp-per-row over fp16 row of 2048, in-place ---
__global__ void softmax_kernel(__half* __restrict__ sc) {
    const int lane = threadIdx.x & 31;
    const size_t row = (size_t)blockIdx.x * 8 + (threadIdx.x >> 5);
    __half* p = sc + row * (size_t)S_LEN;

    uint4 raw[8];
    float f[64];
    #pragma unroll
    for (int i = 0; i < 8; i++) {
        raw[i] = ((uint4*)p)[lane + i * 32];
        const __half2* hp = (const __half2*)&raw[i];
        #pragma unroll
        for (int l = 0; l < 4; l++) {
            float2 t = __half22float2(hp[l]);
            f[i * 8 + l * 2] = t.x; f[i * 8 + l * 2 + 1] = t.y;
        }
    }
    float m = f[0];
    #pragma unroll
    for (int i = 1; i < 64; i++) m = fmaxf(m, f[i]);
    m = warp_max(m);
    float s = 0.0f;
    #pragma unroll
    for (int i = 0; i < 64; i++) { f[i] = expf(f[i] - m); s += f[i]; }
    s = warp_sum(s);
    float inv = 1.0f / s;
    #pragma unroll
    for (int i = 0; i < 8; i++) {
        __half2* hp = (__half2*)&raw[i];
        #pragma unroll
        for (int l = 0; l < 4; l++)
            hp[l] = __floats2half2_rn(f[i * 8 + l * 2] * inv,
                                      f[i * 8 + l * 2 + 1] * inv);
        ((uint4*)p)[lane + i * 32] = raw[i];
    }
}

// ---------------- batched weight transpose: all 3 weights in one launch ----
// dst[c][r] = (half)src[r][c]. Per-block decode of which matrix.
// W_attn [1024,3072] -> waT [3072,1024]: 96x32 col/row tiles = 3072 blocks
// W_fc   [1024,4096] -> wfT [4096,1024]: 128x32          = 4096 blocks
// W_proj [4096,1024] -> wpT [1024,4096]: 32x128          = 4096 blocks
__global__ void transpose3_kernel(const float* __restrict__ wa, __half* __restrict__ waT,
                                  const float* __restrict__ wf, __half* __restrict__ wfT,
                                  const float* __restrict__ wp, __half* __restrict__ wpT) {
    __shared__ float t[32][33];
    int id = blockIdx.x;
    const float* src;
    __half* dst;
    int lds, ldd, bxi, byi;
    if (id < 3072) {                 // W_attn: grid 96(cols) x 32(rows)
        src = wa; dst = waT; lds = 3072; ldd = 1024;
        bxi = id % 96; byi = id / 96;
    } else if (id < 3072 + 4096) {   // W_fc: grid 128 x 32
        id -= 3072;
        src = wf; dst = wfT; lds = 4096; ldd = 1024;
        bxi = id % 128; byi = id / 128;
    } else {                          // W_proj: grid 32 x 128
        id -= 3072 + 4096;
        src = wp; dst = wpT; lds = 1024; ldd = 4096;
        bxi = id % 32; byi = id / 32;
    }
    int bx = bxi * 32, by = byi * 32;
    int tx = threadIdx.x, ty = threadIdx.y;
    #pragma unroll
    for (int i = 0; i < 4; i++)
        t[ty + i * 8][tx] = src[(size_t)(by + ty + i * 8) * lds + bx + tx];
    __syncthreads();
    #pragma unroll
    for (int i = 0; i < 4; i++)
        dst[(size_t)(bx + ty + i * 8) * ldd + by + tx] = (__half)t[tx][ty + i * 8];
}

// =================== fp16 mma.sync GEMM, 128x128x32, 3-stage, occ 2 ========
// C = act(alpha * A @ op(B) + bias) (+ residual)
// A [M,K] fp16 row-major.
// TRANSB=0: B [N,K] row-major (K-major), normal ldmatrix.
// TRANSB=1: B [K,N] row-major (N-major), ldmatrix.trans (e.g. V in qkv).
#define LDH 40                         /* A: 32 + 8 pad halves; 80 B stride */
#define LDBT 136                       /* trans-B: 128 + 8 pad; 272 B stride */
#define NSTAGE 3
#define A_BYTES (128 * LDH * 2)        /* 10240 */
#define BN_BYTES (128 * LDH * 2)       /* 10240: [n][k] */
#define BT_BYTES (32 * LDBT * 2)       /* 8704:  [k][n] */

template <bool TRANSB, bool BIAS, int ACT, bool RES, bool OUT16>
__global__ __launch_bounds__(256, 2)
void hgemm(const __half* __restrict__ A, const __half* __restrict__ B,
           const float* __restrict__ bias, const float* __restrict__ res,
           void* __restrict__ Cv,
           int K, int lda, int ldb, int ldc, int ldres,
           size_t sA, size_t sB, size_t sC, size_t sR, float alpha) {
    constexpr int B_BYTES = TRANSB ? BT_BYTES : BN_BYTES;
    constexpr int STAGE_BYTES = A_BYTES + B_BYTES;

    extern __shared__ char dsm[];
    const uint32_t sbase = (uint32_t)__cvta_generic_to_shared(dsm);

    const int bn = blockIdx.x, bm = blockIdx.y, bz = blockIdx.z;
    const __half* Ab = A + sA * bz + (size_t)bm * 128 * lda;
    const __half* Bb = TRANSB ? (B + sB * bz + (size_t)bn * 128)
                              : (B + sB * bz + (size_t)bn * 128 * ldb);

    const int tid  = threadIdx.x;
    const int lane = tid & 31;
    const int warp = tid >> 5;
    const int wm   = warp >> 1;
    const int wn   = warp & 1;

    const uint32_t a_off = (uint32_t)((lane & 15) * 80 + (lane >> 4) * 16);
    const uint32_t bn_row = (uint32_t)(((lane >> 4) << 3) + (lane & 7));
    const uint32_t bn_off = (uint32_t)(bn_row * 80 + ((lane >> 3) & 1) * 16);
    const uint32_t bt_off = (uint32_t)((lane & 15) * 272 + (lane >> 4) * 16);

    float acc[2][8][4];
    #pragma unroll
    for (int i = 0; i < 2; i++)
        #pragma unroll
        for (int j = 0; j < 8; j++)
            #pragma unroll
            for (int l = 0; l < 4; l++) acc[i][j][l] = 0.0f;

    const int T = K >> 5;

    auto stage = [&](int kt, int s) {
        const int k0 = kt << 5;
        const uint32_t sa = sbase + s * STAGE_BYTES;
        const uint32_t sb = sa + A_BYTES;
        const __half* gA = Ab + (size_t)(tid >> 1) * lda + k0 + (tid & 1) * 16;
        const uint32_t dA = sa + (tid >> 1) * 80 + (tid & 1) * 32;
        cp16(dA, gA);
        cp16(dA + 16, gA + 8);
        if (TRANSB) {
            const int kr = tid >> 3;
            const __half* gB = Bb + (size_t)(k0 + kr) * ldb + (tid & 7) * 16;
            const uint32_t dB = sb + kr * 272 + (tid & 7) * 32;
            cp16(dB, gB);
            cp16(dB + 16, gB + 8);
        } else {
            const __half* gB = Bb + (size_t)(tid >> 1) * ldb + k0 + (tid & 1) * 16;
            const uint32_t dB = sb + (tid >> 1) * 80 + (tid & 1) * 32;
            cp16(dB, gB);
            cp16(dB + 16, gB + 8);
        }
    };

    #pragma unroll
    for (int s = 0; s < NSTAGE; s++) {
        if (s < T) stage(s, s);
        asm volatile("cp.async.commit_group;" ::: "memory");
    }

    int buf = 0;
    for (int kt = 0; kt < T; kt++) {
        asm volatile("cp.async.wait_group %0;" :: "n"(NSTAGE - 1) : "memory");
        __syncthreads();

        const uint32_t sa = sbase + buf * STAGE_BYTES;
        const uint32_t sb = sa + A_BYTES;

        #pragma unroll
        for (int ks = 0; ks < 2; ks++) {
            uint32_t a[2][4];
            #pragma unroll
            for (int am = 0; am < 2; am++) {
                uint32_t addr = sa + (uint32_t)((wm * 32 + am * 16) * 80)
                              + a_off + ks * 32;
                asm volatile(
                    "ldmatrix.sync.aligned.m8n8.x4.shared.b16 {%0,%1,%2,%3}, [%4];"
                    : "=r"(a[am][0]), "=r"(a[am][1]), "=r"(a[am][2]), "=r"(a[am][3])
                    : "r"(addr));
            }
            uint32_t b[8][2];
            #pragma unroll
            for (int t = 0; t < 4; t++) {
                uint32_t r0, r1, r2, r3;
                if (TRANSB) {
                    uint32_t addr = sb + (uint32_t)(ks * 16 * 272)
                                  + (uint32_t)((wn * 64 + t * 16) * 2) + bt_off;
                    asm volatile(
                        "ldmatrix.sync.aligned.m8n8.x4.trans.shared.b16 {%0,%1,%2,%3}, [%4];"
                        : "=r"(r0), "=r"(r1), "=r"(r2), "=r"(r3)
                        : "r"(addr));
                } else {
                    uint32_t addr = sb + (uint32_t)((wn * 64 + t * 16) * 80)
                                  + bn_off + ks * 32;
                    asm volatile(
                        "ldmatrix.sync.aligned.m8n8.x4.shared.b16 {%0,%1,%2,%3}, [%4];"
                        : "=r"(r0), "=r"(r1), "=r"(r2), "=r"(r3)
                        : "r"(addr));
                }
                b[2 * t][0] = r0; b[2 * t][1] = r1;
                b[2 * t + 1][0] = r2; b[2 * t + 1][1] = r3;
            }
            #pragma unroll
            for (int am = 0; am < 2; am++)
                #pragma unroll
                for (int an = 0; an < 8; an++) {
                    asm volatile(
                        "mma.sync.aligned.m16n8k16.row.col.f32.f16.f16.f32 "
                        "{%0,%1,%2,%3}, {%4,%5,%6,%7}, {%8,%9}, {%0,%1,%2,%3};"
                        : "+f"(acc[am][an][0]), "+f"(acc[am][an][1]),
                          "+f"(acc[am][an][2]), "+f"(acc[am][an][3])
                        : "r"(a[am][0]), "r"(a[am][1]), "r"(a[am][2]), "r"(a[am][3]),
                          "r"(b[an][0]), "r"(b[an][1]));
                }
        }
        __syncthreads();
        if (kt + NSTAGE < T) stage(kt + NSTAGE, buf);
        asm volatile("cp.async.commit_group;" ::: "memory");
        buf = (buf + 1 == NSTAGE) ? 0 : buf + 1;
    }

    // ---- epilogue ----
    const int q  = lane >> 2;
    const int r2 = (lane & 3) * 2;
    #pragma unroll
    for (int am = 0; am < 2; am++) {
        int row0 = bm * 128 + wm * 32 + am * 16 + q;
        int row1 = row0 + 8;
        #pragma unroll
        for (int an = 0; an < 8; an++) {
            int col = bn * 128 + wn * 64 + an * 8 + r2;
            float v00 = acc[am][an][0] * alpha;
            float v01 = acc[am][an][1] * alpha;
            float v10 = acc[am][an][2] * alpha;
            float v11 = acc[am][an][3] * alpha;
            if (BIAS) {
                float2 bv = *(const float2*)(bias + col);
                v00 += bv.x; v01 += bv.y; v10 += bv.x; v11 += bv.y;
            }
            if (ACT == 1) {
                v00 = gelu_exact(v00); v01 = gelu_exact(v01);
                v10 = gelu_exact(v10); v11 = gelu_exact(v11);
            }
            if (RES) {
                float2 r0 = *(const float2*)(res + sR * bz + (size_t)row0 * ldres + col);
                float2 r1 = *(const float2*)(res + sR * bz + (size_t)row1 * ldres + col);
                v00 += r0.x; v01 += r0.y; v10 += r1.x; v11 += r1.y;
            }
            if (OUT16) {
                __half* Cb = (__half*)Cv + sC * bz;
                *(__half2*)(Cb + (size_t)row0 * ldc + col) = __floats2half2_rn(v00, v01);
                *(__half2*)(Cb + (size_t)row1 * ldc + col) = __floats2half2_rn(v10, v11);
            } else {
                float* Cb = (float*)Cv + sC * bz;
                *(float2*)(Cb + (size_t)row0 * ldc + col) = make_float2(v00, v01);
                *(float2*)(Cb + (size_t)row1 * ldc + col) = make_float2(v10, v11);
            }
        }
    }
}

#define GSMEM_N (NSTAGE * (A_BYTES + BN_BYTES))   /* 61440 */
#define GSMEM_T (NSTAGE * (A_BYTES + BT_BYTES))   /* 56832 */

// ---------------- launch ----------------
extern "C" void kernel_launch(void* const* d_in, const int* in_sizes, int n_in,
                              void* d_out, int out_size) {
    const float* x      = (const float*)d_in[0];
    const float* ln1_w  = (const float*)d_in[1];
    const float* ln1_b  = (const float*)d_in[2];
    const float* W_attn = (const float*)d_in[3];
    const float* b_attn = (const float*)d_in[4];
    const float* ln2_w  = (const float*)d_in[5];
    const float* ln2_b  = (const float*)d_in[6];
    const float* W_fc   = (const float*)d_in[7];
    const float* b_fc   = (const float*)d_in[8];
    const float* W_proj = (const float*)d_in[9];
    const float* b_proj = (const float*)d_in[10];
    float* out = (float*)d_out;

    void* p;
    cudaGetSymbolAddress(&p, g_h16);    __half* h    = (__half*)p;
    cudaGetSymbolAddress(&p, g_qkv16);  __half* qkv  = (__half*)p;
    cudaGetSymbolAddress(&p, g_sc16);   __half* sc   = (__half*)p;
    cudaGetSymbolAddress(&p, g_x2h);    __half* x2   = (__half*)p;
    cudaGetSymbolAddress(&p, g_fc16);   __half* fcb  = (__half*)p;
    cudaGetSymbolAddress(&p, g_waT16);  __half* waT  = (__half*)p;
    cudaGetSymbolAddress(&p, g_wfT16);  __half* wfT  = (__half*)p;
    cudaGetSymbolAddress(&p, g_wpT16);  __half* wpT  = (__half*)p;

    cudaFuncSetAttribute(hgemm<false, true, 0, false, true>,
                         cudaFuncAttributeMaxDynamicSharedMemorySize, GSMEM_N);
    cudaFuncSetAttribute(hgemm<false, false, 0, false, true>,
                         cudaFuncAttributeMaxDynamicSharedMemorySize, GSMEM_N);
    cudaFuncSetAttribute(hgemm<true, false, 0, true, true>,
                         cudaFuncAttributeMaxDynamicSharedMemorySize, GSMEM_T);
    cudaFuncSetAttribute(hgemm<false, true, 1, false, true>,
                         cudaFuncAttributeMaxDynamicSharedMemorySize, GSMEM_N);
    cudaFuncSetAttribute(hgemm<false, true, 0, false, false>,
                         cudaFuncAttributeMaxDynamicSharedMemorySize, GSMEM_N);

    dim3 blk(256);
    dim3 tblk(32, 8);

    // all 3 weight transposes in ONE launch (fp32 -> fp16, K-major)
    transpose3_kernel<<<3072 + 4096 + 4096, tblk>>>(
        W_attn, waT, W_fc, wfT, W_proj, wpT);

    // 1) h = LN1(x) -> fp16  (warp-per-row, coalesced)
    ln_kernel<float><<<ROWS / 8, blk>>>(x, ln1_w, ln1_b, h);

    // 2) qkv = h @ W_attn + b_attn -> fp16 [16384,3072]
    hgemm<false, true, 0, false, true><<<dim3(24, 128, 1), blk, GSMEM_N>>>(
        h, waT, b_attn, nullptr, qkv,
        1024, 1024, 1024, 3072, 0, 0, 0, 0, 0, 1.0f);

    // 3) scores = (q @ k^T)/sqrt(D) -> fp16
    hgemm<false, false, 0, false, true><<<dim3(16, 16, 8), blk, GSMEM_N>>>(
        qkv, qkv + 1024, nullptr, nullptr, sc,
        1024, 3072, 3072, 2048, 0,
        (size_t)S_LEN * 3072, (size_t)S_LEN * 3072, (size_t)S_LEN * S_LEN, 0,
        0.03125f);

    // 4) softmax (warp-per-row, coalesced, fp16 in/out)
    softmax_kernel<<<ROWS / 8, blk>>>(sc);

    // 5) x2 = x + attn @ V -> fp16  (trans-B: V = qkv[:, 2048:] as [K,N])
    hgemm<true, false, 0, true, true><<<dim3(8, 16, 8), blk, GSMEM_T>>>(
        sc, qkv + 2048, nullptr, x, x2,
        2048, 2048, 3072, 1024, 1024,
        (size_t)S_LEN * S_LEN, (size_t)S_LEN * 3072,
        (size_t)S_LEN * 1024, (size_t)S_LEN * 1024, 1.0f);

    // 6) h = LN2(x2) -> fp16  (warp-per-row, coalesced, fp16 input)
    ln_kernel<__half><<<ROWS / 8, blk>>>(x2, ln2_w, ln2_b, h);

    // 7) fc = gelu(h @ W_fc + b_fc) -> fp16 [16384,4096]
    hgemm<false, true, 1, false, true><<<dim3(32, 128, 1), blk, GSMEM_N>>>(
        h, wfT, b_fc, nullptr, fcb,
        1024, 1024, 1024, 4096, 0, 0, 0, 0, 0, 1.0f);

    // 8) out = fc @ W_proj + b_proj -> fp32 [16384,1024]
    hgemm<false, true, 0, false, false><<<dim3(8, 128, 1), blk, GSMEM_N>>>(
        fcb, wpT, b_proj, nullptr, out,
        4096, 4096, 4096, 1024, 0, 0, 0, 0, 0, 1.0f);
}

// round 16
// speedup vs baseline: 1.0272x; 1.0060x over previous
#include <cuda_runtime.h>
#include <cuda_fp16.h>
#include <math.h>
#include <stdint.h>

#define D_MODEL 1024
#define B_SZ    8
#define S_LEN   2048
#define ROWS    (B_SZ * S_LEN)   /* 16384 */

// ---------------- scratch (device globals) ----------------
__device__ __half g_h16[(size_t)ROWS * D_MODEL];
__device__ __half g_qkv16[(size_t)ROWS * 3 * D_MODEL];
__device__ __half g_sc16[(size_t)B_SZ * S_LEN * S_LEN];
__device__ __half g_x2h[(size_t)ROWS * D_MODEL];
__device__ __half g_fc16[(size_t)ROWS * 4 * D_MODEL];
__device__ __half g_waT16[(size_t)3072 * 1024];
__device__ __half g_wfT16[(size_t)4096 * 1024];
__device__ __half g_wpT16[(size_t)1024 * 4096];

// ---------------- helpers ----------------
__device__ __forceinline__ float gelu_exact(float x) {
    return 0.5f * x * (1.0f + erff(x * 0.70710678118654752f));
}
__device__ __forceinline__ float warp_sum(float v) {
    #pragma unroll
    for (int o = 16; o; o >>= 1) v += __shfl_xor_sync(0xffffffffu, v, o);
    return v;
}
__device__ __forceinline__ float warp_max(float v) {
    #pragma unroll
    for (int o = 16; o; o >>= 1) v = fmaxf(v, __shfl_xor_sync(0xffffffffu, v, o));
    return v;
}
// .cg: bypass L1 on global->smem staging (L1TEX is the GEMM bottleneck;
// operand reuse lives in L2, which has headroom)
__device__ __forceinline__ void cp16(uint32_t dst_smem, const void* gptr) {
    asm volatile("cp.async.cg.shared.global [%0], [%1], 16;"
                 :: "r"(dst_smem), "l"(gptr) : "memory");
}

// ---------------- LayerNorm, warp-per-row, coalesced ----------------
// 256 thr = 8 warps = 8 rows per block. No block barriers.
template <typename TI>
__global__ void ln_kernel(const TI* __restrict__ x, const float* __restrict__ w,
                          const float* __restrict__ b, __half* __restrict__ out) {
    const int lane = threadIdx.x & 31;
    const size_t row = (size_t)blockIdx.x * 8 + (threadIdx.x >> 5);
    __half* op = out + row * D_MODEL;

    float f[32];
    if (sizeof(TI) == 4) {
        const float* xp = (const float*)x + row * D_MODEL;
        #pragma unroll
        for (int j = 0; j < 8; j++) {
            float4 v = *(const float4*)(xp + lane * 4 + j * 128);
            f[j * 4 + 0] = v.x; f[j * 4 + 1] = v.y;
            f[j * 4 + 2] = v.z; f[j * 4 + 3] = v.w;
        }
    } else {
        const __half* xp = (const __half*)x + row * D_MODEL;
        #pragma unroll
        for (int j = 0; j < 4; j++) {
            uint4 raw = *(const uint4*)(xp + lane * 8 + j * 256);
            const __half2* hp = (const __half2*)&raw;
            #pragma unroll
            for (int l = 0; l < 4; l++) {
                float2 t = __half22float2(hp[l]);
                f[j * 8 + l * 2] = t.x; f[j * 8 + l * 2 + 1] = t.y;
            }
        }
    }

    float s = 0.0f, ss = 0.0f;
    #pragma unroll
    for (int i = 0; i < 32; i++) { s += f[i]; ss += f[i] * f[i]; }
    s  = warp_sum(s);
    ss = warp_sum(ss);
    float mu  = s * (1.0f / D_MODEL);
    float var = ss * (1.0f / D_MODEL) - mu * mu;
    float inv = rsqrtf(var + 1e-5f);

    if (sizeof(TI) == 4) {
        #pragma unroll
        for (int j = 0; j < 8; j++) {
            int base = lane * 4 + j * 128;
            float4 wv = *(const float4*)(w + base);
            float4 bv = *(const float4*)(b + base);
            uint2 st;
            __half2* hp = (__half2*)&st;
            hp[0] = __floats2half2_rn((f[j * 4 + 0] - mu) * inv * wv.x + bv.x,
                                      (f[j * 4 + 1] - mu) * inv * wv.y + bv.y);
            hp[1] = __floats2half2_rn((f[j * 4 + 2] - mu) * inv * wv.z + bv.z,
                                      (f[j * 4 + 3] - mu) * inv * wv.w + bv.w);
            *(uint2*)(op + base) = st;
        }
    } else {
        #pragma unroll
        for (int j = 0; j < 4; j++) {
            int base = lane * 8 + j * 256;
            uint4 st;
            __half2* hp = (__half2*)&st;
            #pragma unroll
            for (int l = 0; l < 4; l++) {
                float2 wv = *(const float2*)(w + base + l * 2);
                float2 bv = *(const float2*)(b + base + l * 2);
                hp[l] = __floats2half2_rn(
                    (f[j * 8 + l * 2] - mu) * inv * wv.x + bv.x,
                    (f[j * 8 + l * 2 + 1] - mu) * inv * wv.y + bv.y);
            }
            *(uint4*)(op + base) = st;
        }
    }
}

// ---------------- Softmax, warp-per-row over fp16 row of 2048, in-place ---
__global__ void softmax_kernel(__half* __restrict__ sc) {
    const int lane = threadIdx.x & 31;
    const size_t row = (size_t)blockIdx.x * 8 + (threadIdx.x >> 5);
    __half* p = sc + row * (size_t)S_LEN;

    uint4 raw[8];
    float f[64];
    #pragma unroll
    for (int i = 0; i < 8; i++) {
        raw[i] = ((uint4*)p)[lane + i * 32];
        const __half2* hp = (const __half2*)&raw[i];
        #pragma unroll
        for (int l = 0; l < 4; l++) {
            float2 t = __half22float2(hp[l]);
            f[i * 8 + l * 2] = t.x; f[i * 8 + l * 2 + 1] = t.y;
        }
    }
    float m = f[0];
    #pragma unroll
    for (int i = 1; i < 64; i++) m = fmaxf(m, f[i]);
    m = warp_max(m);
    float s = 0.0f;
    #pragma unroll
    for (int i = 0; i < 64; i++) { f[i] = expf(f[i] - m); s += f[i]; }
    s = warp_sum(s);
    float inv = 1.0f / s;
    #pragma unroll
    for (int i = 0; i < 8; i++) {
        __half2* hp = (__half2*)&raw[i];
        #pragma unroll
        for (int l = 0; l < 4; l++)
            hp[l] = __floats2half2_rn(f[i * 8 + l * 2] * inv,
                                      f[i * 8 + l * 2 + 1] * inv);
        ((uint4*)p)[lane + i * 32] = raw[i];
    }
}

// ---------------- batched weight transpose: all 3 weights in one launch ----
__global__ void transpose3_kernel(const float* __restrict__ wa, __half* __restrict__ waT,
                                  const float* __restrict__ wf, __half* __restrict__ wfT,
                                  const float* __restrict__ wp, __half* __restrict__ wpT) {
    __shared__ float t[32][33];
    int id = blockIdx.x;
    const float* src;
    __half* dst;
    int lds, ldd, bxi, byi;
    if (id < 3072) {                 // W_attn: grid 96(cols) x 32(rows)
        src = wa; dst = waT; lds = 3072; ldd = 1024;
        bxi = id % 96; byi = id / 96;
    } else if (id < 3072 + 4096) {   // W_fc: grid 128 x 32
        id -= 3072;
        src = wf; dst = wfT; lds = 4096; ldd = 1024;
        bxi = id % 128; byi = id / 128;
    } else {                          // W_proj: grid 32 x 128
        id -= 3072 + 4096;
        src = wp; dst = wpT; lds = 1024; ldd = 4096;
        bxi = id % 32; byi = id / 32;
    }
    int bx = bxi * 32, by = byi * 32;
    int tx = threadIdx.x, ty = threadIdx.y;
    #pragma unroll
    for (int i = 0; i < 4; i++)
        t[ty + i * 8][tx] = src[(size_t)(by + ty + i * 8) * lds + bx + tx];
    __syncthreads();
    #pragma unroll
    for (int i = 0; i < 4; i++)
        dst[(size_t)(bx + ty + i * 8) * ldd + by + tx] = (__half)t[tx][ty + i * 8];
}

// =================== fp16 mma.sync GEMM, 128x128x32, 3-stage, occ 2 ========
// C = act(alpha * A @ op(B) + bias) (+ residual)
// A [M,K] fp16 row-major.
// TRANSB=0: B [N,K] row-major (K-major), normal ldmatrix.
// TRANSB=1: B [K,N] row-major (N-major), ldmatrix.trans (e.g. V in qkv).
#define LDH 40                         /* A: 32 + 8 pad halves; 80 B stride */
#define LDBT 136                       /* trans-B: 128 + 8 pad; 272 B stride */
#define NSTAGE 3
#define A_BYTES (128 * LDH * 2)        /* 10240 */
#define BN_BYTES (128 * LDH * 2)       /* 10240: [n][k] */
#define BT_BYTES (32 * LDBT * 2)       /* 8704:  [k][n] */

template <bool TRANSB, bool BIAS, int ACT, bool RES, bool OUT16>
__global__ __launch_bounds__(256, 2)
void hgemm(const __half* __restrict__ A, const __half* __restrict__ B,
           const float* __restrict__ bias, const float* __restrict__ res,
           void* __restrict__ Cv,
           int K, int lda, int ldb, int ldc, int ldres,
           size_t sA, size_t sB, size_t sC, size_t sR, float alpha) {
    constexpr int B_BYTES = TRANSB ? BT_BYTES : BN_BYTES;
    constexpr int STAGE_BYTES = A_BYTES + B_BYTES;

    extern __shared__ char dsm[];
    const uint32_t sbase = (uint32_t)__cvta_generic_to_shared(dsm);

    const int bn = blockIdx.x, bm = blockIdx.y, bz = blockIdx.z;
    const __half* Ab = A + sA * bz + (size_t)bm * 128 * lda;
    const __half* Bb = TRANSB ? (B + sB * bz + (size_t)bn * 128)
                              : (B + sB * bz + (size_t)bn * 128 * ldb);

    const int tid  = threadIdx.x;
    const int lane = tid & 31;
    const int warp = tid >> 5;
    const int wm   = warp >> 1;
    const int wn   = warp & 1;

    const uint32_t a_off = (uint32_t)((lane & 15) * 80 + (lane >> 4) * 16);
    const uint32_t bn_row = (uint32_t)(((lane >> 4) << 3) + (lane & 7));
    const uint32_t bn_off = (uint32_t)(bn_row * 80 + ((lane >> 3) & 1) * 16);
    const uint32_t bt_off = (uint32_t)((lane & 15) * 272 + (lane >> 4) * 16);

    float acc[2][8][4];
    #pragma unroll
    for (int i = 0; i < 2; i++)
        #pragma unroll
        for (int j = 0; j < 8; j++)
            #pragma unroll
            for (int l = 0; l < 4; l++) acc[i][j][l] = 0.0f;

    const int T = K >> 5;

    auto stage = [&](int kt, int s) {
        const int k0 = kt << 5;
        const uint32_t sa = sbase + s * STAGE_BYTES;
        const uint32_t sb = sa + A_BYTES;
        const __half* gA = Ab + (size_t)(tid >> 1) * lda + k0 + (tid & 1) * 16;
        const uint32_t dA = sa + (tid >> 1) * 80 + (tid & 1) * 32;
        cp16(dA, gA);
        cp16(dA + 16, gA + 8);
        if (TRANSB) {
            const int kr = tid >> 3;
            const __half* gB = Bb + (size_t)(k0 + kr) * ldb + (tid & 7) * 16;
            const uint32_t dB = sb + kr * 272 + (tid & 7) * 32;
            cp16(dB, gB);
            cp16(dB + 16, gB + 8);
        } else {
            const __half* gB = Bb + (size_t)(tid >> 1) * ldb + k0 + (tid & 1) * 16;
            const uint32_t dB = sb + (tid >> 1) * 80 + (tid & 1) * 32;
            cp16(dB, gB);
            cp16(dB + 16, gB + 8);
        }
    };

    #pragma unroll
    for (int s = 0; s < NSTAGE; s++) {
        if (s < T) stage(s, s);
        asm volatile("cp.async.commit_group;" ::: "memory");
    }

    int buf = 0;
    for (int kt = 0; kt < T; kt++) {
        asm volatile("cp.async.wait_group %0;" :: "n"(NSTAGE - 1) : "memory");
        __syncthreads();

        const uint32_t sa = sbase + buf * STAGE_BYTES;
        const uint32_t sb = sa + A_BYTES;

        #pragma unroll
        for (int ks = 0; ks < 2; ks++) {
            uint32_t a[2][4];
            #pragma unroll
            for (int am = 0; am < 2; am++) {
                uint32_t addr = sa + (uint32_t)((wm * 32 + am * 16) * 80)
                              + a_off + ks * 32;
                asm volatile(
                    "ldmatrix.sync.aligned.m8n8.x4.shared.b16 {%0,%1,%2,%3}, [%4];"
                    : "=r"(a[am][0]), "=r"(a[am][1]), "=r"(a[am][2]), "=r"(a[am][3])
                    : "r"(addr));
            }
            uint32_t b[8][2];
            #pragma unroll
            for (int t = 0; t < 4; t++) {
                uint32_t r0, r1, r2, r3;
                if (TRANSB) {
                    uint32_t addr = sb + (uint32_t)(ks * 16 * 272)
                                  + (uint32_t)((wn * 64 + t * 16) * 2) + bt_off;
                    asm volatile(
                        "ldmatrix.sync.aligned.m8n8.x4.trans.shared.b16 {%0,%1,%2,%3}, [%4];"
                        : "=r"(r0), "=r"(r1), "=r"(r2), "=r"(r3)
                        : "r"(addr));
                } else {
                    uint32_t addr = sb + (uint32_t)((wn * 64 + t * 16) * 80)
                                  + bn_off + ks * 32;
                    asm volatile(
                        "ldmatrix.sync.aligned.m8n8.x4.shared.b16 {%0,%1,%2,%3}, [%4];"
                        : "=r"(r0), "=r"(r1), "=r"(r2), "=r"(r3)
                        : "r"(addr));
                }
                b[2 * t][0] = r0; b[2 * t][1] = r1;
                b[2 * t + 1][0] = r2; b[2 * t + 1][1] = r3;
            }
            #pragma unroll
            for (int am = 0; am < 2; am++)
                #pragma unroll
                for (int an = 0; an < 8; an++) {
                    asm volatile(
                        "mma.sync.aligned.m16n8k16.row.col.f32.f16.f16.f32 "
                        "{%0,%1,%2,%3}, {%4,%5,%6,%7}, {%8,%9}, {%0,%1,%2,%3};"
                        : "+f"(acc[am][an][0]), "+f"(acc[am][an][1]),
                          "+f"(acc[am][an][2]), "+f"(acc[am][an][3])
                        : "r"(a[am][0]), "r"(a[am][1]), "r"(a[am][2]), "r"(a[am][3]),
                          "r"(b[an][0]), "r"(b[an][1]));
                }
        }
        __syncthreads();
        if (kt + NSTAGE < T) stage(kt + NSTAGE, buf);
        asm volatile("cp.async.commit_group;" ::: "memory");
        buf = (buf + 1 == NSTAGE) ? 0 : buf + 1;
    }

    // ---- epilogue ----
    const int q  = lane >> 2;
    const int r2 = (lane & 3) * 2;
    #pragma unroll
    for (int am = 0; am < 2; am++) {
        int row0 = bm * 128 + wm * 32 + am * 16 + q;
        int row1 = row0 + 8;
        #pragma unroll
        for (int an = 0; an < 8; an++) {
            int col = bn * 128 + wn * 64 + an * 8 + r2;
            float v00 = acc[am][an][0] * alpha;
            float v01 = acc[am][an][1] * alpha;
            float v10 = acc[am][an][2] * alpha;
            float v11 = acc[am][an][3] * alpha;
            if (BIAS) {
                float2 bv = *(const float2*)(bias + col);
                v00 += bv.x; v01 += bv.y; v10 += bv.x; v11 += bv.y;
            }
            if (ACT == 1) {
                v00 = gelu_exact(v00); v01 = gelu_exact(v01);
                v10 = gelu_exact(v10); v11 = gelu_exact(v11);
            }
            if (RES) {
                float2 r0 = *(const float2*)(res + sR * bz + (size_t)row0 * ldres + col);
                float2 r1 = *(const float2*)(res + sR * bz + (size_t)row1 * ldres + col);
                v00 += r0.x; v01 += r0.y; v10 += r1.x; v11 += r1.y;
            }
            if (OUT16) {
                __half* Cb = (__half*)Cv + sC * bz;
                *(__half2*)(Cb + (size_t)row0 * ldc + col) = __floats2half2_rn(v00, v01);
                *(__half2*)(Cb + (size_t)row1 * ldc + col) = __floats2half2_rn(v10, v11);
            } else {
                float* Cb = (float*)Cv + sC * bz;
                *(float2*)(Cb + (size_t)row0 * ldc + col) = make_float2(v00, v01);
                *(float2*)(Cb + (size_t)row1 * ldc + col) = make_float2(v10, v11);
            }
        }
    }
}

#define GSMEM_N (NSTAGE * (A_BYTES + BN_BYTES))   /* 61440 */
#define GSMEM_T (NSTAGE * (A_BYTES + BT_BYTES))   /* 56832 */

// ---------------- launch ----------------
extern "C" void kernel_launch(void* const* d_in, const int* in_sizes, int n_in,
                              void* d_out, int out_size) {
    const float* x      = (const float*)d_in[0];
    const float* ln1_w  = (const float*)d_in[1];
    const float* ln1_b  = (const float*)d_in[2];
    const float* W_attn = (const float*)d_in[3];
    const float* b_attn = (const float*)d_in[4];
    const float* ln2_w  = (const float*)d_in[5];
    const float* ln2_b  = (const float*)d_in[6];
    const float* W_fc   = (const float*)d_in[7];
    const float* b_fc   = (const float*)d_in[8];
    const float* W_proj = (const float*)d_in[9];
    const float* b_proj = (const float*)d_in[10];
    float* out = (float*)d_out;

    void* p;
    cudaGetSymbolAddress(&p, g_h16);    __half* h    = (__half*)p;
    cudaGetSymbolAddress(&p, g_qkv16);  __half* qkv  = (__half*)p;
    cudaGetSymbolAddress(&p, g_sc16);   __half* sc   = (__half*)p;
    cudaGetSymbolAddress(&p, g_x2h);    __half* x2   = (__half*)p;
    cudaGetSymbolAddress(&p, g_fc16);   __half* fcb  = (__half*)p;
    cudaGetSymbolAddress(&p, g_waT16);  __half* waT  = (__half*)p;
    cudaGetSymbolAddress(&p, g_wfT16);  __half* wfT  = (__half*)p;
    cudaGetSymbolAddress(&p, g_wpT16);  __half* wpT  = (__half*)p;

    cudaFuncSetAttribute(hgemm<false, true, 0, false, true>,
                         cudaFuncAttributeMaxDynamicSharedMemorySize, GSMEM_N);
    cudaFuncSetAttribute(hgemm<false, false, 0, false, true>,
                         cudaFuncAttributeMaxDynamicSharedMemorySize, GSMEM_N);
    cudaFuncSetAttribute(hgemm<true, false, 0, true, true>,
                         cudaFuncAttributeMaxDynamicSharedMemorySize, GSMEM_T);
    cudaFuncSetAttribute(hgemm<false, true, 1, false, true>,
                         cudaFuncAttributeMaxDynamicSharedMemorySize, GSMEM_N);
    cudaFuncSetAttribute(hgemm<false, true, 0, false, false>,
                         cudaFuncAttributeMaxDynamicSharedMemorySize, GSMEM_N);

    dim3 blk(256);
    dim3 tblk(32, 8);

    // all 3 weight transposes in ONE launch (fp32 -> fp16, K-major)
    transpose3_kernel<<<3072 + 4096 + 4096, tblk>>>(
        W_attn, waT, W_fc, wfT, W_proj, wpT);

    // 1) h = LN1(x) -> fp16  (warp-per-row, coalesced)
    ln_kernel<float><<<ROWS / 8, blk>>>(x, ln1_w, ln1_b, h);

    // 2) qkv = h @ W_attn + b_attn -> fp16 [16384,3072]
    hgemm<false, true, 0, false, true><<<dim3(24, 128, 1), blk, GSMEM_N>>>(
        h, waT, b_attn, nullptr, qkv,
        1024, 1024, 1024, 3072, 0, 0, 0, 0, 0, 1.0f);

    // 3) scores = (q @ k^T)/sqrt(D) -> fp16
    hgemm<false, false, 0, false, true><<<dim3(16, 16, 8), blk, GSMEM_N>>>(
        qkv, qkv + 1024, nullptr, nullptr, sc,
        1024, 3072, 3072, 2048, 0,
        (size_t)S_LEN * 3072, (size_t)S_LEN * 3072, (size_t)S_LEN * S_LEN, 0,
        0.03125f);

    // 4) softmax (warp-per-row, coalesced, fp16 in/out)
    softmax_kernel<<<ROWS / 8, blk>>>(sc);

    // 5) x2 = x + attn @ V -> fp16  (trans-B: V = qkv[:, 2048:] as [K,N])
    hgemm<true, false, 0, true, true><<<dim3(8, 16, 8), blk, GSMEM_T>>>(
        sc, qkv + 2048, nullptr, x, x2,
        2048, 2048, 3072, 1024, 1024,
        (size_t)S_LEN * S_LEN, (size_t)S_LEN * 3072,
        (size_t)S_LEN * 1024, (size_t)S_LEN * 1024, 1.0f);

    // 6) h = LN2(x2) -> fp16  (warp-per-row, coalesced, fp16 input)
    ln_kernel<__half><<<ROWS / 8, blk>>>(x2, ln2_w, ln2_b, h);

    // 7) fc = gelu(h @ W_fc + b_fc) -> fp16 [16384,4096]
    hgemm<false, true, 1, false, true><<<dim3(32, 128, 1), blk, GSMEM_N>>>(
        h, wfT, b_fc, nullptr, fcb,
        1024, 1024, 1024, 4096, 0, 0, 0, 0, 0, 1.0f);

    // 8) out = fc @ W_proj + b_proj -> fp32 [16384,1024]
    hgemm<false, true, 0, false, false><<<dim3(8, 128, 1), blk, GSMEM_N>>>(
        fcb, wpT, b_proj, nullptr, out,
        4096, 4096, 4096, 1024, 0, 0, 0, 0, 0, 1.0f);
}

// round 17
// speedup vs baseline: 1.0289x; 1.0016x over previous
#include <cuda_runtime.h>
#include <cuda_fp16.h>
#include <math.h>
#include <stdint.h>

#define D_MODEL 1024
#define B_SZ    8
#define S_LEN   2048
#define ROWS    (B_SZ * S_LEN)   /* 16384 */

// ---------------- scratch (device globals) ----------------
__device__ __half g_h16[(size_t)ROWS * D_MODEL];
__device__ __half g_qkv16[(size_t)ROWS * 3 * D_MODEL];
__device__ __half g_sc16[(size_t)B_SZ * S_LEN * S_LEN];
__device__ __half g_x2h[(size_t)ROWS * D_MODEL];
__device__ __half g_fc16[(size_t)ROWS * 4 * D_MODEL];
__device__ __half g_waT16[(size_t)3072 * 1024];
__device__ __half g_wfT16[(size_t)4096 * 1024];
__device__ __half g_wpT16[(size_t)1024 * 4096];

// ---------------- helpers ----------------
__device__ __forceinline__ float gelu_exact(float x) {
    return 0.5f * x * (1.0f + erff(x * 0.70710678118654752f));
}
__device__ __forceinline__ float warp_sum(float v) {
    #pragma unroll
    for (int o = 16; o; o >>= 1) v += __shfl_xor_sync(0xffffffffu, v, o);
    return v;
}
__device__ __forceinline__ float warp_max(float v) {
    #pragma unroll
    for (int o = 16; o; o >>= 1) v = fmaxf(v, __shfl_xor_sync(0xffffffffu, v, o));
    return v;
}
__device__ __forceinline__ void cp16(uint32_t dst_smem, const void* gptr) {
    asm volatile("cp.async.cg.shared.global [%0], [%1], 16;"
                 :: "r"(dst_smem), "l"(gptr) : "memory");
}

// ---------------- LayerNorm, warp-per-row, coalesced ----------------
template <typename TI>
__global__ void ln_kernel(const TI* __restrict__ x, const float* __restrict__ w,
                          const float* __restrict__ b, __half* __restrict__ out) {
    const int lane = threadIdx.x & 31;
    const size_t row = (size_t)blockIdx.x * 8 + (threadIdx.x >> 5);
    __half* op = out + row * D_MODEL;

    float f[32];
    if (sizeof(TI) == 4) {
        const float* xp = (const float*)x + row * D_MODEL;
        #pragma unroll
        for (int j = 0; j < 8; j++) {
            float4 v = *(const float4*)(xp + lane * 4 + j * 128);
            f[j * 4 + 0] = v.x; f[j * 4 + 1] = v.y;
            f[j * 4 + 2] = v.z; f[j * 4 + 3] = v.w;
        }
    } else {
        const __half* xp = (const __half*)x + row * D_MODEL;
        #pragma unroll
        for (int j = 0; j < 4; j++) {
            uint4 raw = *(const uint4*)(xp + lane * 8 + j * 256);
            const __half2* hp = (const __half2*)&raw;
            #pragma unroll
            for (int l = 0; l < 4; l++) {
                float2 t = __half22float2(hp[l]);
                f[j * 8 + l * 2] = t.x; f[j * 8 + l * 2 + 1] = t.y;
            }
        }
    }

    float s = 0.0f, ss = 0.0f;
    #pragma unroll
    for (int i = 0; i < 32; i++) { s += f[i]; ss += f[i] * f[i]; }
    s  = warp_sum(s);
    ss = warp_sum(ss);
    float mu  = s * (1.0f / D_MODEL);
    float var = ss * (1.0f / D_MODEL) - mu * mu;
    float inv = rsqrtf(var + 1e-5f);

    if (sizeof(TI) == 4) {
        #pragma unroll
        for (int j = 0; j < 8; j++) {
            int base = lane * 4 + j * 128;
            float4 wv = *(const float4*)(w + base);
            float4 bv = *(const float4*)(b + base);
            uint2 st;
            __half2* hp = (__half2*)&st;
            hp[0] = __floats2half2_rn((f[j * 4 + 0] - mu) * inv * wv.x + bv.x,
                                      (f[j * 4 + 1] - mu) * inv * wv.y + bv.y);
            hp[1] = __floats2half2_rn((f[j * 4 + 2] - mu) * inv * wv.z + bv.z,
                                      (f[j * 4 + 3] - mu) * inv * wv.w + bv.w);
            *(uint2*)(op + base) = st;
        }
    } else {
        #pragma unroll
        for (int j = 0; j < 4; j++) {
            int base = lane * 8 + j * 256;
            uint4 st;
            __half2* hp = (__half2*)&st;
            #pragma unroll
            for (int l = 0; l < 4; l++) {
                float2 wv = *(const float2*)(w + base + l * 2);
                float2 bv = *(const float2*)(b + base + l * 2);
                hp[l] = __floats2half2_rn(
                    (f[j * 8 + l * 2] - mu) * inv * wv.x + bv.x,
                    (f[j * 8 + l * 2 + 1] - mu) * inv * wv.y + bv.y);
            }
            *(uint4*)(op + base) = st;
        }
    }
}

// ---------------- Softmax, warp-per-row over fp16 row of 2048, in-place ---
__global__ void softmax_kernel(__half* __restrict__ sc) {
    const int lane = threadIdx.x & 31;
    const size_t row = (size_t)blockIdx.x * 8 + (threadIdx.x >> 5);
    __half* p = sc + row * (size_t)S_LEN;

    uint4 raw[8];
    float f[64];
    #pragma unroll
    for (int i = 0; i < 8; i++) {
        raw[i] = ((uint4*)p)[lane + i * 32];
        const __half2* hp = (const __half2*)&raw[i];
        #pragma unroll
        for (int l = 0; l < 4; l++) {
            float2 t = __half22float2(hp[l]);
            f[i * 8 + l * 2] = t.x; f[i * 8 + l * 2 + 1] = t.y;
        }
    }
    float m = f[0];
    #pragma unroll
    for (int i = 1; i < 64; i++) m = fmaxf(m, f[i]);
    m = warp_max(m);
    float s = 0.0f;
    #pragma unroll
    for (int i = 0; i < 64; i++) { f[i] = expf(f[i] - m); s += f[i]; }
    s = warp_sum(s);
    float inv = 1.0f / s;
    #pragma unroll
    for (int i = 0; i < 8; i++) {
        __half2* hp = (__half2*)&raw[i];
        #pragma unroll
        for (int l = 0; l < 4; l++)
            hp[l] = __floats2half2_rn(f[i * 8 + l * 2] * inv,
                                      f[i * 8 + l * 2 + 1] * inv);
        ((uint4*)p)[lane + i * 32] = raw[i];
    }
}

// ---------------- batched weight transpose: all 3 weights in one launch ----
__global__ void transpose3_kernel(const float* __restrict__ wa, __half* __restrict__ waT,
                                  const float* __restrict__ wf, __half* __restrict__ wfT,
                                  const float* __restrict__ wp, __half* __restrict__ wpT) {
    __shared__ float t[32][33];
    int id = blockIdx.x;
    const float* src;
    __half* dst;
    int lds, ldd, bxi, byi;
    if (id < 3072) {
        src = wa; dst = waT; lds = 3072; ldd = 1024;
        bxi = id % 96; byi = id / 96;
    } else if (id < 3072 + 4096) {
        id -= 3072;
        src = wf; dst = wfT; lds = 4096; ldd = 1024;
        bxi = id % 128; byi = id / 128;
    } else {
        id -= 3072 + 4096;
        src = wp; dst = wpT; lds = 1024; ldd = 4096;
        bxi = id % 32; byi = id / 32;
    }
    int bx = bxi * 32, by = byi * 32;
    int tx = threadIdx.x, ty = threadIdx.y;
    #pragma unroll
    for (int i = 0; i < 4; i++)
        t[ty + i * 8][tx] = src[(size_t)(by + ty + i * 8) * lds + bx + tx];
    __syncthreads();
    #pragma unroll
    for (int i = 0; i < 4; i++)
        dst[(size_t)(bx + ty + i * 8) * ldd + by + tx] = (__half)t[tx][ty + i * 8];
}

// =================== fp16 mma.sync GEMM, 128x128x32, 3-stage, occ 2 ========
// Software-pipelined fragments: B-pair (and ks1 A) LDSM issued BEFORE the
// HMMA group that precedes their use, so crossbar overlaps tensor pipe.
#define LDH 40                         /* A: 32 + 8 pad halves; 80 B stride */
#define LDBT 136                       /* trans-B: 128 + 8 pad; 272 B stride */
#define NSTAGE 3
#define A_BYTES (128 * LDH * 2)        /* 10240 */
#define BN_BYTES (128 * LDH * 2)       /* 10240: [n][k] */
#define BT_BYTES (32 * LDBT * 2)       /* 8704:  [k][n] */

template <bool TRANSB, bool BIAS, int ACT, bool RES, bool OUT16>
__global__ __launch_bounds__(256, 2)
void hgemm(const __half* __restrict__ A, const __half* __restrict__ B,
           const float* __restrict__ bias, const float* __restrict__ res,
           void* __restrict__ Cv,
           int K, int lda, int ldb, int ldc, int ldres,
           size_t sA, size_t sB, size_t sC, size_t sR, float alpha) {
    constexpr int B_BYTES = TRANSB ? BT_BYTES : BN_BYTES;
    constexpr int STAGE_BYTES = A_BYTES + B_BYTES;

    extern __shared__ char dsm[];
    const uint32_t sbase = (uint32_t)__cvta_generic_to_shared(dsm);

    const int bn = blockIdx.x, bm = blockIdx.y, bz = blockIdx.z;
    const __half* Ab = A + sA * bz + (size_t)bm * 128 * lda;
    const __half* Bb = TRANSB ? (B + sB * bz + (size_t)bn * 128)
                              : (B + sB * bz + (size_t)bn * 128 * ldb);

    const int tid  = threadIdx.x;
    const int lane = tid & 31;
    const int warp = tid >> 5;
    const int wm   = warp >> 1;
    const int wn   = warp & 1;

    const uint32_t a_off = (uint32_t)((lane & 15) * 80 + (lane >> 4) * 16);
    const uint32_t bn_row = (uint32_t)(((lane >> 4) << 3) + (lane & 7));
    const uint32_t bn_off = (uint32_t)(bn_row * 80 + ((lane >> 3) & 1) * 16);
    const uint32_t bt_off = (uint32_t)((lane & 15) * 272 + (lane >> 4) * 16);

    float acc[2][8][4];
    #pragma unroll
    for (int i = 0; i < 2; i++)
        #pragma unroll
        for (int j = 0; j < 8; j++)
            #pragma unroll
            for (int l = 0; l < 4; l++) acc[i][j][l] = 0.0f;

    const int T = K >> 5;

    auto stage = [&](int kt, int s) {
        const int k0 = kt << 5;
        const uint32_t sa = sbase + s * STAGE_BYTES;
        const uint32_t sb = sa + A_BYTES;
        const __half* gA = Ab + (size_t)(tid >> 1) * lda + k0 + (tid & 1) * 16;
        const uint32_t dA = sa + (tid >> 1) * 80 + (tid & 1) * 32;
        cp16(dA, gA);
        cp16(dA + 16, gA + 8);
        if (TRANSB) {
            const int kr = tid >> 3;
            const __half* gB = Bb + (size_t)(k0 + kr) * ldb + (tid & 7) * 16;
            const uint32_t dB = sb + kr * 272 + (tid & 7) * 32;
            cp16(dB, gB);
            cp16(dB + 16, gB + 8);
        } else {
            const __half* gB = Bb + (size_t)(tid >> 1) * ldb + k0 + (tid & 1) * 16;
            const uint32_t dB = sb + (tid >> 1) * 80 + (tid & 1) * 32;
            cp16(dB, gB);
            cp16(dB + 16, gB + 8);
        }
    };

    // frag loaders (indexing identical to previous rounds; order is the change)
    auto lds_a_ks = [&](uint32_t (&dst)[2][4], uint32_t sa, int ks) {
        #pragma unroll
        for (int am = 0; am < 2; am++) {
            uint32_t addr = sa + (uint32_t)((wm * 32 + am * 16) * 80)
                          + a_off + ks * 32;
            asm volatile(
                "ldmatrix.sync.aligned.m8n8.x4.shared.b16 {%0,%1,%2,%3}, [%4];"
                : "=r"(dst[am][0]), "=r"(dst[am][1]), "=r"(dst[am][2]), "=r"(dst[am][3])
                : "r"(addr));
        }
    };
    auto lds_bp = [&](uint32_t (&dst)[4], uint32_t sb, int ks, int t) {
        if (TRANSB) {
            uint32_t addr = sb + (uint32_t)(ks * 16 * 272)
                          + (uint32_t)((wn * 64 + t * 16) * 2) + bt_off;
            asm volatile(
                "ldmatrix.sync.aligned.m8n8.x4.trans.shared.b16 {%0,%1,%2,%3}, [%4];"
                : "=r"(dst[0]), "=r"(dst[1]), "=r"(dst[2]), "=r"(dst[3])
                : "r"(addr));
        } else {
            uint32_t addr = sb + (uint32_t)((wn * 64 + t * 16) * 80)
                          + bn_off + ks * 32;
            asm volatile(
                "ldmatrix.sync.aligned.m8n8.x4.shared.b16 {%0,%1,%2,%3}, [%4];"
                : "=r"(dst[0]), "=r"(dst[1]), "=r"(dst[2]), "=r"(dst[3])
                : "r"(addr));
        }
    };

    #pragma unroll
    for (int s = 0; s < NSTAGE; s++) {
        if (s < T) stage(s, s);
        asm volatile("cp.async.commit_group;" ::: "memory");
    }

    int buf = 0;
    for (int kt = 0; kt < T; kt++) {
        asm volatile("cp.async.wait_group %0;" :: "n"(NSTAGE - 1) : "memory");
        __syncthreads();

        const uint32_t sa = sbase + buf * STAGE_BYTES;
        const uint32_t sb = sa + A_BYTES;

        uint32_t Af[2][2][4];   // [ks][am][reg]
        uint32_t Bf[2][4];      // double-buffered b-pair

        lds_a_ks(Af[0], sa, 0);
        lds_bp(Bf[0], sb, 0, 0);

        #pragma unroll
        for (int ks = 0; ks < 2; ks++) {
            #pragma unroll
            for (int t = 0; t < 4; t++) {
                const int pb = (ks * 4 + t) & 1;
                // prefetch next B pair before computing current group
                if (!(ks == 1 && t == 3)) {
                    const int nk = (t == 3) ? ks + 1 : ks;
                    const int nt = (t == 3) ? 0 : t + 1;
                    lds_bp(Bf[pb ^ 1], sb, nk, nt);
                }
                // prefetch ks1 A frags early, overlapped with first HMMA group
                if (ks == 0 && t == 0) lds_a_ks(Af[1], sa, 1);
                // 4 HMMA on current frags
                #pragma unroll
                for (int am = 0; am < 2; am++) {
                    asm volatile(
                        "mma.sync.aligned.m16n8k16.row.col.f32.f16.f16.f32 "
                        "{%0,%1,%2,%3}, {%4,%5,%6,%7}, {%8,%9}, {%0,%1,%2,%3};"
                        : "+f"(acc[am][2 * t][0]), "+f"(acc[am][2 * t][1]),
                          "+f"(acc[am][2 * t][2]), "+f"(acc[am][2 * t][3])
                        : "r"(Af[ks][am][0]), "r"(Af[ks][am][1]),
                          "r"(Af[ks][am][2]), "r"(Af[ks][am][3]),
                          "r"(Bf[pb][0]), "r"(Bf[pb][1]));
                    asm volatile(
                        "mma.sync.aligned.m16n8k16.row.col.f32.f16.f16.f32 "
                        "{%0,%1,%2,%3}, {%4,%5,%6,%7}, {%8,%9}, {%0,%1,%2,%3};"
                        : "+f"(acc[am][2 * t + 1][0]), "+f"(acc[am][2 * t + 1][1]),
                          "+f"(acc[am][2 * t + 1][2]), "+f"(acc[am][2 * t + 1][3])
                        : "r"(Af[ks][am][0]), "r"(Af[ks][am][1]),
                          "r"(Af[ks][am][2]), "r"(Af[ks][am][3]),
                          "r"(Bf[pb][2]), "r"(Bf[pb][3]));
                }
            }
        }
        __syncthreads();
        if (kt + NSTAGE < T) stage(kt + NSTAGE, buf);
        asm volatile("cp.async.commit_group;" ::: "memory");
        buf = (buf + 1 == NSTAGE) ? 0 : buf + 1;
    }

    // ---- epilogue ----
    const int q  = lane >> 2;
    const int r2 = (lane & 3) * 2;
    #pragma unroll
    for (int am = 0; am < 2; am++) {
        int row0 = bm * 128 + wm * 32 + am * 16 + q;
        int row1 = row0 + 8;
        #pragma unroll
        for (int an = 0; an < 8; an++) {
            int col = bn * 128 + wn * 64 + an * 8 + r2;
            float v00 = acc[am][an][0] * alpha;
            float v01 = acc[am][an][1] * alpha;
            float v10 = acc[am][an][2] * alpha;
            float v11 = acc[am][an][3] * alpha;
            if (BIAS) {
                float2 bv = *(const float2*)(bias + col);
                v00 += bv.x; v01 += bv.y; v10 += bv.x; v11 += bv.y;
            }
            if (ACT == 1) {
                v00 = gelu_exact(v00); v01 = gelu_exact(v01);
                v10 = gelu_exact(v10); v11 = gelu_exact(v11);
            }
            if (RES) {
                float2 r0 = *(const float2*)(res + sR * bz + (size_t)row0 * ldres + col);
                float2 r1 = *(const float2*)(res + sR * bz + (size_t)row1 * ldres + col);
                v00 += r0.x; v01 += r0.y; v10 += r1.x; v11 += r1.y;
            }
            if (OUT16) {
                __half* Cb = (__half*)Cv + sC * bz;
                *(__half2*)(Cb + (size_t)row0 * ldc + col) = __floats2half2_rn(v00, v01);
                *(__half2*)(Cb + (size_t)row1 * ldc + col) = __floats2half2_rn(v10, v11);
            } else {
                float* Cb = (float*)Cv + sC * bz;
                *(float2*)(Cb + (size_t)row0 * ldc + col) = make_float2(v00, v01);
                *(float2*)(Cb + (size_t)row1 * ldc + col) = make_float2(v10, v11);
            }
        }
    }
}

#define GSMEM_N (NSTAGE * (A_BYTES + BN_BYTES))   /* 61440 */
#define GSMEM_T (NSTAGE * (A_BYTES + BT_BYTES))   /* 56832 */

// ---------------- launch ----------------
extern "C" void kernel_launch(void* const* d_in, const int* in_sizes, int n_in,
                              void* d_out, int out_size) {
    const float* x      = (const float*)d_in[0];
    const float* ln1_w  = (const float*)d_in[1];
    const float* ln1_b  = (const float*)d_in[2];
    const float* W_attn = (const float*)d_in[3];
    const float* b_attn = (const float*)d_in[4];
    const float* ln2_w  = (const float*)d_in[5];
    const float* ln2_b  = (const float*)d_in[6];
    const float* W_fc   = (const float*)d_in[7];
    const float* b_fc   = (const float*)d_in[8];
    const float* W_proj = (const float*)d_in[9];
    const float* b_proj = (const float*)d_in[10];
    float* out = (float*)d_out;

    void* p;
    cudaGetSymbolAddress(&p, g_h16);    __half* h    = (__half*)p;
    cudaGetSymbolAddress(&p, g_qkv16);  __half* qkv  = (__half*)p;
    cudaGetSymbolAddress(&p, g_sc16);   __half* sc   = (__half*)p;
    cudaGetSymbolAddress(&p, g_x2h);    __half* x2   = (__half*)p;
    cudaGetSymbolAddress(&p, g_fc16);   __half* fcb  = (__half*)p;
    cudaGetSymbolAddress(&p, g_waT16);  __half* waT  = (__half*)p;
    cudaGetSymbolAddress(&p, g_wfT16);  __half* wfT  = (__half*)p;
    cudaGetSymbolAddress(&p, g_wpT16);  __half* wpT  = (__half*)p;

    cudaFuncSetAttribute(hgemm<false, true, 0, false, true>,
                         cudaFuncAttributeMaxDynamicSharedMemorySize, GSMEM_N);
    cudaFuncSetAttribute(hgemm<false, false, 0, false, true>,
                         cudaFuncAttributeMaxDynamicSharedMemorySize, GSMEM_N);
    cudaFuncSetAttribute(hgemm<true, false, 0, true, true>,
                         cudaFuncAttributeMaxDynamicSharedMemorySize, GSMEM_T);
    cudaFuncSetAttribute(hgemm<false, true, 1, false, true>,
                         cudaFuncAttributeMaxDynamicSharedMemorySize, GSMEM_N);
    cudaFuncSetAttribute(hgemm<false, true, 0, false, false>,
                         cudaFuncAttributeMaxDynamicSharedMemorySize, GSMEM_N);

    dim3 blk(256);
    dim3 tblk(32, 8);

    // all 3 weight transposes in ONE launch (fp32 -> fp16, K-major)
    transpose3_kernel<<<3072 + 4096 + 4096, tblk>>>(
        W_attn, waT, W_fc, wfT, W_proj, wpT);

    // 1) h = LN1(x) -> fp16
    ln_kernel<float><<<ROWS / 8, blk>>>(x, ln1_w, ln1_b, h);

    // 2) qkv = h @ W_attn + b_attn -> fp16 [16384,3072]
    hgemm<false, true, 0, false, true><<<dim3(24, 128, 1), blk, GSMEM_N>>>(
        h, waT, b_attn, nullptr, qkv,
        1024, 1024, 1024, 3072, 0, 0, 0, 0, 0, 1.0f);

    // 3) scores = (q @ k^T)/sqrt(D) -> fp16
    hgemm<false, false, 0, false, true><<<dim3(16, 16, 8), blk, GSMEM_N>>>(
        qkv, qkv + 1024, nullptr, nullptr, sc,
        1024, 3072, 3072, 2048, 0,
        (size_t)S_LEN * 3072, (size_t)S_LEN * 3072, (size_t)S_LEN * S_LEN, 0,
        0.03125f);

    // 4) softmax
    softmax_kernel<<<ROWS / 8, blk>>>(sc);

    // 5) x2 = x + attn @ V -> fp16  (trans-B)
    hgemm<true, false, 0, true, true><<<dim3(8, 16, 8), blk, GSMEM_T>>>(
        sc, qkv + 2048, nullptr, x, x2,
        2048, 2048, 3072, 1024, 1024,
        (size_t)S_LEN * S_LEN, (size_t)S_LEN * 3072,
        (size_t)S_LEN * 1024, (size_t)S_LEN * 1024, 1.0f);

    // 6) h = LN2(x2) -> fp16
    ln_kernel<__half><<<ROWS / 8, blk>>>(x2, ln2_w, ln2_b, h);

    // 7) fc = gelu(h @ W_fc + b_fc) -> fp16 [16384,4096]
    hgemm<false, true, 1, false, true><<<dim3(32, 128, 1), blk, GSMEM_N>>>(
        h, wfT, b_fc, nullptr, fcb,
        1024, 1024, 1024, 4096, 0, 0, 0, 0, 0, 1.0f);

    // 8) out = fc @ W_proj + b_proj -> fp32 [16384,1024]
    hgemm<false, true, 0, false, false><<<dim3(8, 128, 1), blk, GSMEM_N>>>(
        fcb, wpT, b_proj, nullptr, out,
        4096, 4096, 4096, 1024, 0, 0, 0, 0, 0, 1.0f);
}